// round 2
// baseline (speedup 1.0000x reference)
#include <cuda_runtime.h>
#include <math.h>

// Problem constants
#define Bx 4
#define Lx 4096
#define Hx 8
#define Ex 64
#define Mx 64
#define Cx 512            // H*E
#define KP 2176           // padded folded K (>= 2049), = 17*128
#define NSPLIT 17
#define KCHUNK 128

typedef unsigned long long u64;

// Static device scratch (no allocations allowed)
__device__ float g_bc[Mx * KP];                 // cos(2*pi*m*l/L), [m][l], pads 0
__device__ float g_bs[Mx * KP];                 // -sin(...),       [m][l], pads 0
__device__ float g_bcT[KP * Mx];                // transposed [l][m]
__device__ float g_bsT[KP * Mx];
__device__ float g_part[8 * NSPLIT * Mx * Cx];  // split-K partials
__device__ float g_X[8 * Mx * Cx];              // X[bp][m][c], bp = b*2 + (0:Re,1:Im)
__device__ float g_res[Bx * Cx * 2 * Mx];       // res[b][c][0..63 ReS, 64..127 ImS]

// packed f32x2 helpers
__device__ __forceinline__ void fma2(u64& d, u64 a, u64 b) {
    asm("fma.rn.f32x2 %0, %1, %2, %0;" : "+l"(d) : "l"(a), "l"(b));
}
__device__ __forceinline__ float2 unpk(u64 v) {
    float2 r;
    asm("mov.b64 {%0, %1}, %2;" : "=f"(r.x), "=f"(r.y) : "l"(v));
    return r;
}

// ---------------------------------------------------------------------------
// K0: build basis tables (both layouts).
// ---------------------------------------------------------------------------
__global__ void k_basis() {
    int id = blockIdx.x * blockDim.x + threadIdx.x;
    if (id >= Mx * KP) return;
    int m = id / KP, l = id - m * KP;
    float c = 0.f, s = 0.f;
    if (l <= 2048) {
        int r = (m * l) & (Lx - 1);
        sincospif((float)r / 2048.0f, &s, &c);
    }
    g_bc[m * KP + l] = c;
    g_bs[m * KP + l] = -s;
    g_bcT[l * Mx + m] = c;
    g_bsT[l * Mx + m] = -s;
}

// ---------------------------------------------------------------------------
// K1: forward GEMM, split-K, fold fused, Re+Im fused, packed FFMA2.
//   Re[m][c] = sum_l bc[m][l] * (q[l]+q[L-l])[c]
//   Im[m][c] = sum_l bs[m][l] * (q[l]-q[L-l])[c]
// Block: 64 m x 64 c, 256 threads (4x4 per thread), K chunk 128.
// ---------------------------------------------------------------------------
__global__ void k_fwd(const float* __restrict__ q) {
    __shared__ float2 Ac[8][64];   // (bc,bc) duplicated pairs
    __shared__ float2 As[8][64];   // (bs,bs)
    __shared__ float2 Bsum[8][32]; // qs natural pairs
    __shared__ float2 Bdif[8][32]; // qd natural pairs

    int t = threadIdx.x;
    int ct = blockIdx.x;      // 0..7
    int split = blockIdx.y;   // 0..16
    int b = blockIdx.z;       // 0..3
    int c0 = ct * 64;
    int k0 = split * KCHUNK;
    int tx = t & 15, ty = t >> 4;

    u64 accRe[4][2], accIm[4][2];
#pragma unroll
    for (int r = 0; r < 4; r++) {
        accRe[r][0] = accRe[r][1] = 0ull;
        accIm[r][0] = accIm[r][1] = 0ull;
    }
    const float* qb = q + (size_t)b * Lx * Cx;

    for (int kc = k0; kc < k0 + KCHUNK; kc += 8) {
        if (t < 128) {
            int kk = t >> 4, cg = t & 15;
            int l = kc + kk;
            float4 a = make_float4(0.f, 0.f, 0.f, 0.f);
            float4 mm = make_float4(0.f, 0.f, 0.f, 0.f);
            bool half = (l == 0) || (l == 2048);
            if (l <= 2048) {
                a = *(const float4*)(qb + (size_t)l * Cx + c0 + cg * 4);
                if (!half)
                    mm = *(const float4*)(qb + (size_t)(Lx - l) * Cx + c0 + cg * 4);
            }
            float4 vs, vd;
            if (half) {
                vs = a; vd = make_float4(0.f, 0.f, 0.f, 0.f);
            } else {
                vs = make_float4(a.x + mm.x, a.y + mm.y, a.z + mm.z, a.w + mm.w);
                vd = make_float4(a.x - mm.x, a.y - mm.y, a.z - mm.z, a.w - mm.w);
            }
            Bsum[kk][cg * 2]     = make_float2(vs.x, vs.y);
            Bsum[kk][cg * 2 + 1] = make_float2(vs.z, vs.w);
            Bdif[kk][cg * 2]     = make_float2(vd.x, vd.y);
            Bdif[kk][cg * 2 + 1] = make_float2(vd.z, vd.w);
        } else {
            int t2 = t - 128;
            int kk = t2 >> 4, mg = t2 & 15;
            int l = kc + kk;
            float4 c4 = *(const float4*)(g_bcT + (size_t)l * Mx + mg * 4);
            float4 s4 = *(const float4*)(g_bsT + (size_t)l * Mx + mg * 4);
            Ac[kk][mg * 4 + 0] = make_float2(c4.x, c4.x);
            Ac[kk][mg * 4 + 1] = make_float2(c4.y, c4.y);
            Ac[kk][mg * 4 + 2] = make_float2(c4.z, c4.z);
            Ac[kk][mg * 4 + 3] = make_float2(c4.w, c4.w);
            As[kk][mg * 4 + 0] = make_float2(s4.x, s4.x);
            As[kk][mg * 4 + 1] = make_float2(s4.y, s4.y);
            As[kk][mg * 4 + 2] = make_float2(s4.z, s4.z);
            As[kk][mg * 4 + 3] = make_float2(s4.w, s4.w);
        }
        __syncthreads();
#pragma unroll
        for (int kk = 0; kk < 8; kk++) {
            u64 b0 = *(const u64*)&Bsum[kk][tx * 2];
            u64 b1 = *(const u64*)&Bsum[kk][tx * 2 + 1];
            u64 d0 = *(const u64*)&Bdif[kk][tx * 2];
            u64 d1 = *(const u64*)&Bdif[kk][tx * 2 + 1];
#pragma unroll
            for (int r = 0; r < 4; r++) {
                u64 ac = *(const u64*)&Ac[kk][ty * 4 + r];
                u64 as = *(const u64*)&As[kk][ty * 4 + r];
                fma2(accRe[r][0], ac, b0);
                fma2(accRe[r][1], ac, b1);
                fma2(accIm[r][0], as, d0);
                fma2(accIm[r][1], as, d1);
            }
        }
        __syncthreads();
    }

    float* oRe = g_part + ((size_t)(b * 2 + 0) * NSPLIT + split) * (Mx * Cx);
    float* oIm = g_part + ((size_t)(b * 2 + 1) * NSPLIT + split) * (Mx * Cx);
#pragma unroll
    for (int r = 0; r < 4; r++) {
        int m = ty * 4 + r;
        float2 lo = unpk(accRe[r][0]), hi = unpk(accRe[r][1]);
        *(float4*)(oRe + (size_t)m * Cx + c0 + tx * 4) =
            make_float4(lo.x, lo.y, hi.x, hi.y);
        float2 lo2 = unpk(accIm[r][0]), hi2 = unpk(accIm[r][1]);
        *(float4*)(oIm + (size_t)m * Cx + c0 + tx * 4) =
            make_float4(lo2.x, lo2.y, hi2.x, hi2.y);
    }
}

// ---------------------------------------------------------------------------
// K2: reduce split-K partials -> g_X (float4)
// ---------------------------------------------------------------------------
__global__ void k_reduce() {
    int o4 = blockIdx.x * blockDim.x + threadIdx.x;  // 0..65535 (float4 units)
    int bp = o4 >> 13;           // 8192 float4 per bp
    int inner = o4 & 8191;
    const float4* p = (const float4*)g_part + (size_t)bp * NSPLIT * 8192 + inner;
    float4 s = make_float4(0.f, 0.f, 0.f, 0.f);
#pragma unroll
    for (int sp = 0; sp < NSPLIT; sp++) {
        float4 v = p[(size_t)sp * 8192];
        s.x += v.x; s.y += v.y; s.z += v.z; s.w += v.w;
    }
    ((float4*)g_X)[o4] = s;
}

// ---------------------------------------------------------------------------
// K3: head mixing + irfft scaling.
// ---------------------------------------------------------------------------
__global__ void k_mix(const float* __restrict__ wr, const float* __restrict__ wi) {
    int t = blockIdx.x * blockDim.x + threadIdx.x;  // 131072 = B*H*E*M
    int m = t & 63;
    int e = (t >> 6) & 63;
    int o = (t >> 12) & 7;
    int b = t >> 15;
    const float* Xre = g_X + ((size_t)(b * 2 + 0) * Mx + m) * Cx + e;
    const float* Xim = g_X + ((size_t)(b * 2 + 1) * Mx + m) * Cx + e;
    float re = 0.f, im = 0.f;
#pragma unroll
    for (int i = 0; i < Hx; i++) {
        float xr = Xre[i * Ex];
        float xi = Xim[i * Ex];
        size_t wIdx = (((size_t)i * Hx + o) * Ex + e) * Mx + m;
        float wre = wr[wIdx], wim = wi[wIdx];
        re += xr * wre - xi * wim;
        im += xr * wim + xi * wre;
    }
    float scR = (m == 0) ? (1.0f / Lx) : (2.0f / Lx);
    float* r = g_res + ((size_t)(b * Cx) + o * Ex + e) * 128;
    r[m] = re * scR;
    r[64 + m] = (m == 0) ? 0.f : im * (2.0f / Lx);
}

// ---------------------------------------------------------------------------
// K4: inverse synthesis with mirror writes, packed FFMA2.
//   E[l] = sum_m ReS*bc[m][l];  O[l] = sum_m ImS*bs[m][l]
//   out[l] = E+O (l=0..2047); out[L-l] = E-O (l=1..2047)
// Block: 32 rows x 128 l, 256 threads, 4 rows x 4 l per thread.
// Basis staged via smem in 16-mode chunks.
// ---------------------------------------------------------------------------
__global__ void k_inv(float* __restrict__ out) {
    __shared__ float2 sa[32][128];   // duplicated (v,v): [row][m] / [row][64+m]
    __shared__ float sbc[16][128];
    __shared__ float sbs[16][128];
    int t = threadIdx.x;
    int ltile = blockIdx.x;            // 0..15
    int rowBase = blockIdx.y * 32;     // rows 0..2047
    int l0b = ltile * 128;

    // load res tile (duplicated pairs)
#pragma unroll
    for (int s = 0; s < 4; s++) {
        int i4 = t + 256 * s;          // 1024 float4 loads
        int r = i4 >> 5, j4 = i4 & 31;
        float4 v = *(const float4*)(g_res + (size_t)(rowBase + r) * 128 + j4 * 4);
        sa[r][j4 * 4 + 0] = make_float2(v.x, v.x);
        sa[r][j4 * 4 + 1] = make_float2(v.y, v.y);
        sa[r][j4 * 4 + 2] = make_float2(v.z, v.z);
        sa[r][j4 * 4 + 3] = make_float2(v.w, v.w);
    }

    int tx = t & 31, ty = t >> 5;
    int l0 = l0b + tx * 4;
    u64 E[4][2], O[4][2];
#pragma unroll
    for (int r = 0; r < 4; r++) {
        E[r][0] = E[r][1] = 0ull;
        O[r][0] = O[r][1] = 0ull;
    }

    for (int ch = 0; ch < 4; ch++) {
        __syncthreads();   // also covers initial sa stores
#pragma unroll
        for (int s = 0; s < 2; s++) {
            int i4 = t + 256 * s;       // 512 float4 per table
            int mr = i4 >> 5, j4 = i4 & 31;
            *(float4*)&sbc[mr][j4 * 4] =
                *(const float4*)(g_bc + (size_t)(ch * 16 + mr) * KP + l0b + j4 * 4);
            *(float4*)&sbs[mr][j4 * 4] =
                *(const float4*)(g_bs + (size_t)(ch * 16 + mr) * KP + l0b + j4 * 4);
        }
        __syncthreads();
#pragma unroll
        for (int mm = 0; mm < 16; mm++) {
            int m = ch * 16 + mm;
            u64 c0p = *(const u64*)&sbc[mm][tx * 4];
            u64 c1p = *(const u64*)&sbc[mm][tx * 4 + 2];
            u64 s0p = *(const u64*)&sbs[mm][tx * 4];
            u64 s1p = *(const u64*)&sbs[mm][tx * 4 + 2];
#pragma unroll
            for (int r = 0; r < 4; r++) {
                u64 ar = *(const u64*)&sa[ty * 4 + r][m];
                u64 ai = *(const u64*)&sa[ty * 4 + r][64 + m];
                fma2(E[r][0], ar, c0p);
                fma2(E[r][1], ar, c1p);
                fma2(O[r][0], ai, s0p);
                fma2(O[r][1], ai, s1p);
            }
        }
    }

#pragma unroll
    for (int r = 0; r < 4; r++) {
        int row = rowBase + ty * 4 + r;
        float2 e0 = unpk(E[r][0]), e1 = unpk(E[r][1]);
        float2 o0 = unpk(O[r][0]), o1 = unpk(O[r][1]);
        float4 v = make_float4(e0.x + o0.x, e0.y + o0.y, e1.x + o1.x, e1.y + o1.y);
        *(float4*)(out + (size_t)row * Lx + l0) = v;
        float ev[4] = {e0.x, e0.y, e1.x, e1.y};
        float ov[4] = {o0.x, o0.y, o1.x, o1.y};
#pragma unroll
        for (int u = 0; u < 4; u++) {
            int l = l0 + u;
            if (l > 0) out[(size_t)row * Lx + (Lx - l)] = ev[u] - ov[u];
        }
    }
}

// ---------------------------------------------------------------------------
// K5: l = 2048 edge. bc[m][2048] = (-1)^m, bs = 0.
// ---------------------------------------------------------------------------
__global__ void k_edge(float* __restrict__ out) {
    int row = blockIdx.x * blockDim.x + threadIdx.x;  // 0..2047
    const float* r = g_res + (size_t)row * 128;
    float s = 0.f;
#pragma unroll
    for (int m = 0; m < 64; m += 2) { s += r[m]; s -= r[m + 1]; }
    out[(size_t)row * Lx + 2048] = s;
}

// ---------------------------------------------------------------------------
extern "C" void kernel_launch(void* const* d_in, const int* in_sizes, int n_in,
                              void* d_out, int out_size) {
    const float* q  = (const float*)d_in[0];
    // d_in[1]=k, d_in[2]=v unused by reference
    const float* wr = (const float*)d_in[3];
    const float* wi = (const float*)d_in[4];
    float* out = (float*)d_out;

    k_basis<<<(Mx * KP + 255) / 256, 256>>>();
    {
        dim3 g(8, NSPLIT, Bx);
        k_fwd<<<g, 256>>>(q);
    }
    k_reduce<<<256, 256>>>();
    k_mix<<<(Bx * Hx * Ex * Mx) / 256, 256>>>(wr, wi);
    {
        dim3 g(16, 64);
        k_inv<<<g, 256>>>(out);
    }
    k_edge<<<8, 256>>>(out);
}